// round 14
// baseline (speedup 1.0000x reference)
#include <cuda_runtime.h>
#include <cuda_fp16.h>
#include <cstdint>

#define BSZ   256
#define MM    128
#define NN    1024
#define ITERS 100
#define ALPHA 0.1f

__device__ __half g_Ah[(size_t)BSZ * MM * NN];
__device__ float  g_C [(size_t)BSZ * MM * MM];   // AAT -> inverse (in place)

__device__ __forceinline__ uint32_t smem_u32(const void* p) {
    uint32_t a;
    asm("{ .reg .u64 t; cvta.to.shared.u64 t, %1; cvt.u32.u64 %0, t; }" : "=r"(a) : "l"(p));
    return a;
}
__device__ __forceinline__ uint32_t mapa_rank(uint32_t addr, uint32_t trank) {
    uint32_t r;
    asm("mapa.shared::cluster.u32 %0, %1, %2;" : "=r"(r) : "r"(addr), "r"(trank));
    return r;
}
__device__ __forceinline__ void cluster_sync_() {
    asm volatile("barrier.cluster.arrive.aligned;" ::: "memory");
    asm volatile("barrier.cluster.wait.aligned;"   ::: "memory");
}
__device__ __forceinline__ void st_cluster_f32(uint32_t addr, float v) {
    asm volatile("st.shared::cluster.f32 [%0], %1;" :: "r"(addr), "f"(v) : "memory");
}
__device__ __forceinline__ void st_cluster_u32(uint32_t addr, uint32_t v) {
    asm volatile("st.shared::cluster.u32 [%0], %1;" :: "r"(addr), "r"(v) : "memory");
}
__device__ __forceinline__ void mbar_init(uint32_t a, uint32_t c) {
    asm volatile("mbarrier.init.shared.b64 [%0], %1;" :: "r"(a), "r"(c) : "memory");
}
__device__ __forceinline__ void mbar_arrive_remote(uint32_t ra) {
    asm volatile("mbarrier.arrive.release.cluster.shared::cluster.b64 _, [%0];" :: "r"(ra) : "memory");
}
__device__ __forceinline__ void mbar_arrive_local(uint32_t la) {
    asm volatile("mbarrier.arrive.shared.b64 _, [%0];" :: "r"(la) : "memory");
}
__device__ __forceinline__ void mbar_wait_acq(uint32_t mb, uint32_t par) {
    asm volatile(
        "{\n\t.reg .pred P;\n\t"
        "WL%=:\n\t"
        "mbarrier.try_wait.parity.acquire.cluster.shared::cta.b64 P, [%0], %1, 0x989680;\n\t"
        "@P bra.uni WD%=;\n\t"
        "bra.uni WL%=;\n\t"
        "WD%=:\n\t}" :: "r"(mb), "r"(par) : "memory");
}
__device__ __forceinline__ void ldsm_x4(uint32_t& a0, uint32_t& a1, uint32_t& a2, uint32_t& a3, uint32_t addr) {
    asm volatile("ldmatrix.sync.aligned.m8n8.x4.shared.b16 {%0,%1,%2,%3}, [%4];"
                 : "=r"(a0), "=r"(a1), "=r"(a2), "=r"(a3) : "r"(addr));
}
__device__ __forceinline__ void ldsm_x4t(uint32_t& a0, uint32_t& a1, uint32_t& a2, uint32_t& a3, uint32_t addr) {
    asm volatile("ldmatrix.sync.aligned.m8n8.x4.trans.shared.b16 {%0,%1,%2,%3}, [%4];"
                 : "=r"(a0), "=r"(a1), "=r"(a2), "=r"(a3) : "r"(addr));
}
__device__ __forceinline__ void mma16816(float& c0, float& c1, float& c2, float& c3,
                                         uint32_t a0, uint32_t a1, uint32_t a2, uint32_t a3,
                                         uint32_t b0, uint32_t b1) {
    asm volatile("mma.sync.aligned.m16n8k16.row.col.f32.f16.f16.f32 "
                 "{%0,%1,%2,%3},{%4,%5,%6,%7},{%8,%9},{%0,%1,%2,%3};"
                 : "+f"(c0), "+f"(c1), "+f"(c2), "+f"(c3)
                 : "r"(a0), "r"(a1), "r"(a2), "r"(a3), "r"(b0), "r"(b1));
}

// --------------------------------------------------------------------------
__global__ void k_convert(const float* __restrict__ A) {
    size_t i = ((size_t)blockIdx.x * blockDim.x + threadIdx.x) * 4;
    float4 v = *(const float4*)(A + i);
    __half2* dst = (__half2*)(g_Ah + i);
    dst[0] = __floats2half2_rn(v.x, v.y);
    dst[1] = __floats2half2_rn(v.z, v.w);
}

// k_aat (HMMA, verified R9) --------------------------------------------------
#define AT_PITCH_B 272
__global__ void __launch_bounds__(256) k_aat() {
    __shared__ __half tile[128 * (AT_PITCH_B / 2)];
    const int b = blockIdx.x, t = threadIdx.x, w = t >> 5, l = t & 31;
    const __half* Ab = g_Ah + (size_t)b * MM * NN;
    const uint32_t tbase = smem_u32(tile);

    float acc[16][4];
#pragma unroll
    for (int nt = 0; nt < 16; nt++)
#pragma unroll
        for (int q = 0; q < 4; q++) acc[nt][q] = 0.0f;

    const int m0 = w * 16;
    const uint32_t aAddr = tbase + (uint32_t)(m0 + (l & 15)) * AT_PITCH_B
                         + (uint32_t)((l >> 4) << 4);
    const int bg = l >> 3;
    const uint32_t bAddr0 = tbase + (uint32_t)((l & 7) + ((bg >> 1) << 3)) * AT_PITCH_B
                          + (uint32_t)((bg & 1) << 4);

    for (int kc = 0; kc < 8; kc++) {
#pragma unroll
        for (int q = 0; q < 8; q++) {
            int i = t + 256 * q, r = i >> 4, c4 = i & 15;
            *(uint4*)((char*)tile + r * AT_PITCH_B + c4 * 16) =
                *(const uint4*)(Ab + (size_t)r * NN + kc * 128 + c4 * 8);
        }
        __syncthreads();

#pragma unroll
        for (int kt = 0; kt < 8; kt++) {
            uint32_t a0, a1, a2, a3;
            ldsm_x4(a0, a1, a2, a3, aAddr + (uint32_t)(kt * 32));
#pragma unroll
            for (int nt = 0; nt < 16; nt += 2) {
                uint32_t r0, r1, r2, r3;
                ldsm_x4(r0, r1, r2, r3,
                        bAddr0 + (uint32_t)(nt * 8) * AT_PITCH_B + (uint32_t)(kt * 32));
                mma16816(acc[nt][0],   acc[nt][1],   acc[nt][2],   acc[nt][3],
                         a0, a1, a2, a3, r0, r1);
                mma16816(acc[nt+1][0], acc[nt+1][1], acc[nt+1][2], acc[nt+1][3],
                         a0, a1, a2, a3, r2, r3);
            }
        }
        __syncthreads();
    }

    float* Cb = g_C + (size_t)b * MM * MM;
    const int r0 = m0 + (l >> 2), c0 = 2 * (l & 3);
#pragma unroll
    for (int nt = 0; nt < 16; nt++) {
        *(float2*)&Cb[(size_t)r0 * MM + nt * 8 + c0]       = make_float2(acc[nt][0], acc[nt][1]);
        *(float2*)&Cb[(size_t)(r0 + 8) * MM + nt * 8 + c0] = make_float2(acc[nt][2], acc[nt][3]);
    }
}

// Gauss-Jordan inverse, 512 threads (verified R10 setup win) -----------------
__global__ void __launch_bounds__(512) k_inv() {
    extern __shared__ float sm[];
    float* sM = sm; float* sf = sm + 16384; float* sp = sm + 16512;
    int b = blockIdx.x, t = threadIdx.x;
    float* Cb = g_C + (size_t)b * MM * MM;
    for (int i = t; i < 4096; i += 512) ((float4*)sM)[i] = ((const float4*)Cb)[i];
    __syncthreads();
    for (int k = 0; k < 128; k++) {
        if (t == 0) sp[0] = 1.0f / sM[k * 128 + k];
        __syncthreads();
        float ipiv = sp[0];
        if (t < 128) {
            float v = sM[k * 128 + t];
            sM[k * 128 + t] = (t == k) ? ipiv : v * ipiv;
            sf[t] = (t == k) ? 0.0f : sM[t * 128 + k];
        }
        __syncthreads();
        int j = t & 127, g = t >> 7;
        float mk = sM[k * 128 + j];
#pragma unroll 4
        for (int ii = 0; ii < 32; ii++) {
            int i = g * 32 + ii;
            if (i == k) continue;
            float fi = sf[i];
            float v = sM[i * 128 + j];
            sM[i * 128 + j] = (j == k) ? (-fi * mk) : (v - fi * mk);
        }
        __syncthreads();
    }
    for (int i = t; i < 4096; i += 512) ((float4*)Cb)[i] = ((const float4*)sM)[i];
}

// Iterations: 4-CTA cluster per batch, A quarter per CTA, occupancy 2 --------
// smem layout (words):
#define APITCH_U4 33                   // 528 bytes/row (16B bank step)
#define OFF_A    0                     // 128*33*4 = 16896 w (66 KB)
#define OFF_C    16896                 // 4096 f (32-row C slice)
#define OFF_YH   20992                 // 128 u32 (256 local cols half2 hi)
#define OFF_YL   21120                 // 128 u32
#define OFF_B    21248                 // 128 f
#define OFF_REM  21376                 // 2 bufs x 4 ranks x 128 f = 1024 f
#define OFF_RT   22400                 // 128 f
#define OFF_UH   22528                 // 2 bufs x 64 u32 (full u, half2 hi)
#define OFF_UL   22656                 // 2 bufs x 64 u32
#define OFF_CORR 22784                 // 256 f
#define OFF_MB   23040                 // 4 mbars (pass1[2], u[2]) = 8 w
#define SMEM_WORDS 23048               // 92192 bytes -> 2 CTAs/SM

__global__ void __launch_bounds__(256, 2) __cluster_dims__(4, 1, 1)
k_iter(const float* __restrict__ bvec, const float* __restrict__ D1,
       const float* __restrict__ D2, float* __restrict__ out) {
    extern __shared__ float sm[];
    const int t = threadIdx.x, w = t >> 5, l = t & 31;
    const int b = blockIdx.x >> 2;
    const uint32_t rank = blockIdx.x & 3;
    const uint32_t sbase = smem_u32(sm);
    // peer smem bases (3 peers)
    uint32_t pb[3];
    {
        int pi = 0;
#pragma unroll
        for (uint32_t r = 0; r < 4; r++)
            if (r != rank) pb[pi++] = mapa_rank(sbase, r);
    }
    const uint32_t aA = sbase + OFF_A * 4u;

    {   // load A quarter (padded), C slice, b
        uint4* da = (uint4*)(sm + OFF_A);
        const uint4* sa = (const uint4*)(g_Ah + (size_t)b * MM * NN + (size_t)rank * 256);
#pragma unroll
        for (int q = 0; q < 16; q++) {
            int i = t + 256 * q, r = i >> 5, c4 = i & 31;   // 128 rows x 32 uint4
            da[r * APITCH_U4 + c4] = sa[(size_t)r * 128 + c4];
        }
        float4* dc = (float4*)(sm + OFF_C);
        const float4* sc = (const float4*)(g_C + (size_t)b * MM * MM + (size_t)rank * 32 * MM);
#pragma unroll
        for (int q = 0; q < 4; q++) dc[t + 256 * q] = sc[t + 256 * q];
        if (t < 128) sm[OFF_B + t] = bvec[(size_t)b * MM + t];
        if (t == 0) {
            mbar_init(sbase + (OFF_MB + 0) * 4u, 256);   // pass1 buf0: 64x4 arrivals
            mbar_init(sbase + (OFF_MB + 2) * 4u, 256);   // pass1 buf1
            mbar_init(sbase + (OFF_MB + 4) * 4u, 64);    // u buf0: 16x4 arrivals
            mbar_init(sbase + (OFF_MB + 6) * 4u, 64);    // u buf1
        }
    }

    // per-thread state: t<128 owns local cols 2t, 2t+1 (global 256*rank + 2t)
    float2 thr2 = make_float2(0.f, 0.f), dv2 = make_float2(0.f, 0.f);
    float2 z2 = make_float2(0.f, 0.f), xh2, yv2 = make_float2(0.f, 0.f);
    if (t < 128) {
        float2 d1 = ((const float2*)(D1 + (size_t)b * NN + rank * 256))[t];
        float2 d2 = ((const float2*)(D2 + (size_t)b * NN + rank * 256))[t];
        thr2.x = ALPHA * fabsf(d1.x); thr2.y = ALPHA * fabsf(d1.y);
        dv2.x = 1.0f / (1.0f + 2.0f * ALPHA * d2.x * d2.x);
        dv2.y = 1.0f / (1.0f + 2.0f * ALPHA * d2.y * d2.y);
    }
    __syncthreads();
    cluster_sync_();   // mbar init visible cluster-wide

    // pass1: warp w -> rows 16w..16w+15, k = all 256 local cols
    const int p1_m0 = w * 16;
    const uint32_t p1_addr = aA + (uint32_t)(p1_m0 + (l & 15)) * 528u
                           + (uint32_t)((l >> 4) << 4);
    const int bc = l & 3;
    // pass2: warp w -> col-tiles 2w, 2w+1 of local 256 cols
    const uint32_t p2_rowoff = (uint32_t)((l & 7) + ((l >> 4) << 3)) * 528u
                             + (uint32_t)((l & 8) << 1);

    for (int it = 0; it < ITERS; it++) {
        const int buf = it & 1;
        const uint32_t par = (uint32_t)((it >> 1) & 1);
        // --- elementwise (t<128): soft-threshold, y, split hi/lo ---
        if (t < 128) {
            float a0 = z2.x - thr2.x, c0 = z2.x + thr2.x;
            float a1 = z2.y - thr2.y, c1 = z2.y + thr2.y;
            xh2.x = (a0 > 0.f) ? a0 * dv2.x : ((c0 < 0.f) ? c0 * dv2.x : 0.f);
            xh2.y = (a1 > 0.f) ? a1 * dv2.y : ((c1 < 0.f) ? c1 * dv2.y : 0.f);
            yv2.x = 2.0f * xh2.x - z2.x;
            yv2.y = 2.0f * xh2.y - z2.y;
            __half2 hy = __floats2half2_rn(yv2.x, yv2.y);
            float2 fy = __half22float2(hy);
            __half2 ly = __floats2half2_rn(yv2.x - fy.x, yv2.y - fy.y);
            ((uint32_t*)(sm + OFF_YH))[t] = *(uint32_t*)&hy;
            ((uint32_t*)(sm + OFF_YL))[t] = *(uint32_t*)&ly;
        }
        __syncthreads();                                   // bar1: y ready

        // --- pass 1 (HMMA): r_partial = A_q * y_q; push to all 4 REM slots ---
        {
            float ch0 = 0.f, ch1 = 0.f, ch2 = 0.f, ch3 = 0.f;
            float cl0 = 0.f, cl1 = 0.f, cl2 = 0.f, cl3 = 0.f;
            const uint32_t* yh = (const uint32_t*)(sm + OFF_YH);
            const uint32_t* yl = (const uint32_t*)(sm + OFF_YL);
            uint32_t addr = p1_addr;
#pragma unroll
            for (int kt = 0; kt < 16; kt++) {
                uint32_t a0, a1, a2, a3;
                ldsm_x4(a0, a1, a2, a3, addr);
                addr += 32u;                                // +16 halves
                int kb = kt * 8 + bc;
                mma16816(ch0, ch1, ch2, ch3, a0, a1, a2, a3, yh[kb], yh[kb + 4]);
                mma16816(cl0, cl1, cl2, cl3, a0, a1, a2, a3, yl[kb], yl[kb + 4]);
            }
            if ((l & 3) == 0) {
                float r0 = ch0 + cl0, r1 = ch2 + cl2;
                int row0 = p1_m0 + (l >> 2), row1 = row0 + 8;
                uint32_t off = (uint32_t)(OFF_REM + buf * 512 + rank * 128);
                sm[off + row0] = r0;                       // local slot (own rank)
                sm[off + row1] = r1;
#pragma unroll
                for (int p = 0; p < 3; p++) {
                    st_cluster_f32(pb[p] + (off + (uint32_t)row0) * 4u, r0);
                    st_cluster_f32(pb[p] + (off + (uint32_t)row1) * 4u, r1);
                }
#pragma unroll
                for (int p = 0; p < 3; p++)
                    mbar_arrive_remote(pb[p] + (uint32_t)(OFF_MB + 2 * buf) * 4u);
                mbar_arrive_local(sbase + (uint32_t)(OFF_MB + 2 * buf) * 4u);
            }
        }

        // --- rt (t<128): wait 256 arrivals, sum 4 slots - b ---
        if (t < 128) {
            mbar_wait_acq(sbase + (uint32_t)(OFF_MB + 2 * buf) * 4u, par);
            int o = OFF_REM + buf * 512;
            sm[OFF_RT + t] = sm[o + t] + sm[o + 128 + t] + sm[o + 256 + t]
                           + sm[o + 384 + t] - sm[OFF_B + t];
        }
        __syncthreads();                                   // bar3: rt ready

        // --- u slice (rows 32*rank + i_loc): 8 lanes/row, conflict-free ---
        {
            int i_loc = t >> 3, h = t & 7;
            float accu = 0.0f;
#pragma unroll
            for (int m = 0; m < 4; m++) {
                int j = 4 * h + 32 * m;
                float4 c4 = *(const float4*)(sm + OFF_C + i_loc * 128 + j);
                float4 r4 = *(const float4*)(sm + OFF_RT + j);
                accu += c4.x * r4.x + c4.y * r4.y + c4.z * r4.z + c4.w * r4.w;
            }
            accu += __shfl_xor_sync(0xffffffffu, accu, 1);
            accu += __shfl_xor_sync(0xffffffffu, accu, 2);
            accu += __shfl_xor_sync(0xffffffffu, accu, 4);  // all 8 lanes hold u_i
            float un = __shfl_down_sync(0xffffffffu, accu, 8);  // u_{i+1}
            if ((t & 15) == 0) {                            // 16 writers
                __half2 hu = __floats2half2_rn(accu, un);
                float2 fu = __half22float2(hu);
                __half2 lu = __floats2half2_rn(accu - fu.x, un - fu.y);
                uint32_t widx = 16u * rank + (uint32_t)(t >> 4);
                uint32_t oh = (uint32_t)(OFF_UH + buf * 64) + widx;
                uint32_t ol = (uint32_t)(OFF_UL + buf * 64) + widx;
                ((uint32_t*)sm)[oh] = *(uint32_t*)&hu;      // local
                ((uint32_t*)sm)[ol] = *(uint32_t*)&lu;
#pragma unroll
                for (int p = 0; p < 3; p++) {
                    st_cluster_u32(pb[p] + oh * 4u, *(uint32_t*)&hu);
                    st_cluster_u32(pb[p] + ol * 4u, *(uint32_t*)&lu);
                }
#pragma unroll
                for (int p = 0; p < 3; p++)
                    mbar_arrive_remote(pb[p] + (uint32_t)(OFF_MB + 4 + 2 * buf) * 4u);
                mbar_arrive_local(sbase + (uint32_t)(OFF_MB + 4 + 2 * buf) * 4u);
            }
        }
        // all threads wait for full u (64 arrivals)
        mbar_wait_acq(sbase + (uint32_t)(OFF_MB + 4 + 2 * buf) * 4u, par);

        // --- pass 2 (HMMA trans): corr = A_q^T * u (full 128-row u) ---
        {
            const uint32_t* uh = (const uint32_t*)(sm + OFF_UH + buf * 64);
            const uint32_t* ul = (const uint32_t*)(sm + OFF_UL + buf * 64);
#pragma unroll
            for (int mi = 0; mi < 2; mi++) {
                int cc0 = (2 * w + mi) * 16;
                float dh0 = 0.f, dh1 = 0.f, dh2 = 0.f, dh3 = 0.f;
                float dl0 = 0.f, dl1 = 0.f, dl2 = 0.f, dl3 = 0.f;
                uint32_t addr = aA + p2_rowoff + (uint32_t)(cc0 * 2);
#pragma unroll
                for (int kt = 0; kt < 8; kt++) {
                    uint32_t a0, a1, a2, a3;
                    ldsm_x4t(a0, a1, a2, a3, addr);
                    addr += 16u * 528u;                     // +16 rows
                    int kb = kt * 8 + bc;
                    mma16816(dh0, dh1, dh2, dh3, a0, a1, a2, a3, uh[kb], uh[kb + 4]);
                    mma16816(dl0, dl1, dl2, dl3, a0, a1, a2, a3, ul[kb], ul[kb + 4]);
                }
                if ((l & 3) == 0) {
                    sm[OFF_CORR + cc0 + (l >> 2)]     = dh0 + dl0;
                    sm[OFF_CORR + cc0 + 8 + (l >> 2)] = dh2 + dl2;
                }
            }
        }
        __syncthreads();                                   // bar5: corr ready

        // --- epilogue (t<128): z' = x_half - corr, x_new = y - corr ---
        if (t < 128) {
            float2 cr = *(const float2*)(sm + OFF_CORR + 2 * t);
            z2.x = xh2.x - cr.x; z2.y = xh2.y - cr.y;
            yv2.x -= cr.x; yv2.y -= cr.y;                  // x_new
        }
    }

    if (t < 128)
        ((float2*)(out + (size_t)b * NN + rank * 256))[t] = yv2;
    cluster_sync_();
}

// --------------------------------------------------------------------------
extern "C" void kernel_launch(void* const* d_in, const int* in_sizes, int n_in,
                              void* d_out, int out_size) {
    const float* A  = (const float*)d_in[0];
    const float* bv = (const float*)d_in[1];
    const float* D1 = (const float*)d_in[2];
    const float* D2 = (const float*)d_in[3];
    float* out = (float*)d_out;

    cudaFuncSetAttribute(k_inv,  cudaFuncAttributeMaxDynamicSharedMemorySize, 66052);
    cudaFuncSetAttribute(k_iter, cudaFuncAttributeMaxDynamicSharedMemorySize, SMEM_WORDS * 4);

    k_convert<<<32768, 256>>>(A);
    k_aat<<<BSZ, 256>>>();
    k_inv<<<BSZ, 512, 66052>>>();
    k_iter<<<BSZ * 4, 256, SMEM_WORDS * 4>>>(bv, D1, D2, out);
}

// round 15
// speedup vs baseline: 1.1679x; 1.1679x over previous
#include <cuda_runtime.h>
#include <cuda_fp16.h>
#include <cstdint>

#define BSZ   256
#define MM    128
#define NN    1024
#define ITERS 100
#define ALPHA 0.1f

__device__ __half g_Ah[(size_t)BSZ * MM * NN];
__device__ float  g_C [(size_t)BSZ * MM * MM];   // AAT -> inverse (in place)

__device__ __forceinline__ uint32_t smem_u32(const void* p) {
    uint32_t a;
    asm("{ .reg .u64 t; cvta.to.shared.u64 t, %1; cvt.u32.u64 %0, t; }" : "=r"(a) : "l"(p));
    return a;
}
__device__ __forceinline__ uint32_t mapa_rank(uint32_t addr, uint32_t trank) {
    uint32_t r;
    asm("mapa.shared::cluster.u32 %0, %1, %2;" : "=r"(r) : "r"(addr), "r"(trank));
    return r;
}
__device__ __forceinline__ void cluster_sync_() {
    asm volatile("barrier.cluster.arrive.aligned;" ::: "memory");
    asm volatile("barrier.cluster.wait.aligned;"   ::: "memory");
}
__device__ __forceinline__ void st_cluster_f32(uint32_t addr, float v) {
    asm volatile("st.shared::cluster.f32 [%0], %1;" :: "r"(addr), "f"(v) : "memory");
}
__device__ __forceinline__ void mbar_init(uint32_t a, uint32_t c) {
    asm volatile("mbarrier.init.shared.b64 [%0], %1;" :: "r"(a), "r"(c) : "memory");
}
__device__ __forceinline__ void mbar_arrive_remote(uint32_t ra) {
    asm volatile("mbarrier.arrive.release.cluster.shared::cluster.b64 _, [%0];" :: "r"(ra) : "memory");
}
__device__ __forceinline__ void mbar_wait_acq(uint32_t mb, uint32_t par) {
    asm volatile(
        "{\n\t.reg .pred P;\n\t"
        "WL%=:\n\t"
        "mbarrier.try_wait.parity.acquire.cluster.shared::cta.b64 P, [%0], %1, 0x989680;\n\t"
        "@P bra.uni WD%=;\n\t"
        "bra.uni WL%=;\n\t"
        "WD%=:\n\t}" :: "r"(mb), "r"(par) : "memory");
}
__device__ __forceinline__ void ldsm_x4(uint32_t& a0, uint32_t& a1, uint32_t& a2, uint32_t& a3, uint32_t addr) {
    asm volatile("ldmatrix.sync.aligned.m8n8.x4.shared.b16 {%0,%1,%2,%3}, [%4];"
                 : "=r"(a0), "=r"(a1), "=r"(a2), "=r"(a3) : "r"(addr));
}
__device__ __forceinline__ void ldsm_x4t(uint32_t& a0, uint32_t& a1, uint32_t& a2, uint32_t& a3, uint32_t addr) {
    asm volatile("ldmatrix.sync.aligned.m8n8.x4.trans.shared.b16 {%0,%1,%2,%3}, [%4];"
                 : "=r"(a0), "=r"(a1), "=r"(a2), "=r"(a3) : "r"(addr));
}
__device__ __forceinline__ void mma16816(float& c0, float& c1, float& c2, float& c3,
                                         uint32_t a0, uint32_t a1, uint32_t a2, uint32_t a3,
                                         uint32_t b0, uint32_t b1) {
    asm volatile("mma.sync.aligned.m16n8k16.row.col.f32.f16.f16.f32 "
                 "{%0,%1,%2,%3},{%4,%5,%6,%7},{%8,%9},{%0,%1,%2,%3};"
                 : "+f"(c0), "+f"(c1), "+f"(c2), "+f"(c3)
                 : "r"(a0), "r"(a1), "r"(a2), "r"(a3), "r"(b0), "r"(b1));
}

// --------------------------------------------------------------------------
// k_aat (HMMA) with FUSED fp32->fp16 conversion: reads fp32 A, converts in
// regs, stores both the smem tile (for MMA) and g_Ah (for k_iter).
// --------------------------------------------------------------------------
#define AT_PITCH_B 272
__global__ void __launch_bounds__(256) k_aat(const float* __restrict__ A32) {
    __shared__ __half tile[128 * (AT_PITCH_B / 2)];
    const int b = blockIdx.x, t = threadIdx.x, w = t >> 5, l = t & 31;
    const uint32_t tbase = smem_u32(tile);
    uint2* gah = (uint2*)(g_Ah + (size_t)b * MM * NN);

    float acc[16][4];
#pragma unroll
    for (int nt = 0; nt < 16; nt++)
#pragma unroll
        for (int q = 0; q < 4; q++) acc[nt][q] = 0.0f;

    const int m0 = w * 16;
    const uint32_t aAddr = tbase + (uint32_t)(m0 + (l & 15)) * AT_PITCH_B
                         + (uint32_t)((l >> 4) << 4);
    const int bg = l >> 3;
    const uint32_t bAddr0 = tbase + (uint32_t)((l & 7) + ((bg >> 1) << 3)) * AT_PITCH_B
                          + (uint32_t)((bg & 1) << 4);

    for (int kc = 0; kc < 8; kc++) {
        // fused convert: 4096 float4 (fp32) -> tile fp16 + g_Ah fp16
#pragma unroll
        for (int q = 0; q < 16; q++) {
            int i = t + 256 * q, r = i >> 5, c4 = i & 31;     // 32 float4/row
            float4 v = *(const float4*)(A32 + ((size_t)(b * MM + r)) * NN + kc * 128 + c4 * 4);
            uint2 hv;
            __half2 h0 = __floats2half2_rn(v.x, v.y);
            __half2 h1 = __floats2half2_rn(v.z, v.w);
            hv.x = *(uint32_t*)&h0; hv.y = *(uint32_t*)&h1;
            *(uint2*)((char*)tile + r * AT_PITCH_B + c4 * 8) = hv;
            gah[(size_t)r * 256 + kc * 32 + c4] = hv;
        }
        __syncthreads();

#pragma unroll
        for (int kt = 0; kt < 8; kt++) {
            uint32_t a0, a1, a2, a3;
            ldsm_x4(a0, a1, a2, a3, aAddr + (uint32_t)(kt * 32));
#pragma unroll
            for (int nt = 0; nt < 16; nt += 2) {
                uint32_t r0, r1, r2, r3;
                ldsm_x4(r0, r1, r2, r3,
                        bAddr0 + (uint32_t)(nt * 8) * AT_PITCH_B + (uint32_t)(kt * 32));
                mma16816(acc[nt][0],   acc[nt][1],   acc[nt][2],   acc[nt][3],
                         a0, a1, a2, a3, r0, r1);
                mma16816(acc[nt+1][0], acc[nt+1][1], acc[nt+1][2], acc[nt+1][3],
                         a0, a1, a2, a3, r2, r3);
            }
        }
        __syncthreads();
    }

    float* Cb = g_C + (size_t)b * MM * MM;
    const int r0 = m0 + (l >> 2), c0 = 2 * (l & 3);
#pragma unroll
    for (int nt = 0; nt < 16; nt++) {
        *(float2*)&Cb[(size_t)r0 * MM + nt * 8 + c0]       = make_float2(acc[nt][0], acc[nt][1]);
        *(float2*)&Cb[(size_t)(r0 + 8) * MM + nt * 8 + c0] = make_float2(acc[nt][2], acc[nt][3]);
    }
}

// Gauss-Jordan inverse, 512 threads (verified) --------------------------------
__global__ void __launch_bounds__(512) k_inv() {
    extern __shared__ float sm[];
    float* sM = sm; float* sf = sm + 16384; float* sp = sm + 16512;
    int b = blockIdx.x, t = threadIdx.x;
    float* Cb = g_C + (size_t)b * MM * MM;
    for (int i = t; i < 4096; i += 512) ((float4*)sM)[i] = ((const float4*)Cb)[i];
    __syncthreads();
    for (int k = 0; k < 128; k++) {
        if (t == 0) sp[0] = 1.0f / sM[k * 128 + k];
        __syncthreads();
        float ipiv = sp[0];
        if (t < 128) {
            float v = sM[k * 128 + t];
            sM[k * 128 + t] = (t == k) ? ipiv : v * ipiv;
            sf[t] = (t == k) ? 0.0f : sM[t * 128 + k];
        }
        __syncthreads();
        int j = t & 127, g = t >> 7;
        float mk = sM[k * 128 + j];
#pragma unroll 4
        for (int ii = 0; ii < 32; ii++) {
            int i = g * 32 + ii;
            if (i == k) continue;
            float fi = sf[i];
            float v = sM[i * 128 + j];
            sM[i * 128 + j] = (j == k) ? (-fi * mk) : (v - fi * mk);
        }
        __syncthreads();
    }
    for (int i = t; i < 4096; i += 512) ((float4*)Cb)[i] = ((const float4*)sM)[i];
}

// Iterations: R12 champion core, ONE k_iter change: 512-thread conflict-free
// u-stage (4 lanes/row). ------------------------------------------------------
#define APAD_U4  65
#define OFF_C    0                     // 16384 f
#define OFF_A    16384                 // 33280 w (128*260 u32)
#define OFF_YH   49664                 // 256 u32 (half2 y_hi)
#define OFF_YL   49920                 // 256 u32
#define OFF_B    50176                 // 128 f
#define OFF_SR0  50304                 // 128 f (khalf 0 partial)
#define OFF_SR1  50432                 // 128 f (khalf 1 partial)
#define OFF_REM  50560                 // 256 f (peer partial, 2 bufs)
#define OFF_RT   50816                 // 128 f
#define OFF_UH   50944                 // 64 u32 (half2 u_hi)
#define OFF_UL   51008                 // 64 u32
#define OFF_CORR 51072                 // 512 f
#define OFF_MB   51584                 // 2 x u64 mbarriers
#define SMEM_WORDS 51588               // 206352 bytes

__global__ void __launch_bounds__(512, 1) __cluster_dims__(2, 1, 1)
k_iter(const float* __restrict__ bvec, const float* __restrict__ D1,
       const float* __restrict__ D2, float* __restrict__ out) {
    extern __shared__ float sm[];
    const int t = threadIdx.x, w = t >> 5, l = t & 31;
    const int b = blockIdx.x >> 1;
    const uint32_t rank = blockIdx.x & 1;
    const uint32_t sbase = smem_u32(sm);
    const uint32_t peer = mapa_rank(sbase, rank ^ 1u);
    const uint32_t aA = sbase + OFF_A * 4u;

    {   // load C, padded A-half, b
        float4* d = (float4*)(sm + OFF_C);
        const float4* s = (const float4*)(g_C + (size_t)b * MM * MM);
#pragma unroll
        for (int q = 0; q < 8; q++) d[t + 512 * q] = s[t + 512 * q];
        uint4* da = (uint4*)(sm + OFF_A);
        const uint4* sa = (const uint4*)(g_Ah + (size_t)b * MM * NN + (size_t)rank * 512);
#pragma unroll
        for (int q = 0; q < 16; q++) {
            int i = t + 512 * q, r = i >> 6, c4 = i & 63;
            da[r * APAD_U4 + c4] = sa[(size_t)r * 128 + c4];
        }
        if (t < 128) sm[OFF_B + t] = bvec[(size_t)b * MM + t];
        if (t == 0) {
            mbar_init(sbase + OFF_MB * 4u, 128);
            mbar_init(sbase + OFF_MB * 4u + 8u, 128);
        }
    }

    // per-thread state: t<256 owns local cols 2t, 2t+1
    float2 thr2 = make_float2(0.f, 0.f), dv2 = make_float2(0.f, 0.f);
    float2 z2 = make_float2(0.f, 0.f), xh2, yv2 = make_float2(0.f, 0.f);
    if (t < 256) {
        float2 d1 = ((const float2*)(D1 + (size_t)b * NN + rank * 512))[t];
        float2 d2 = ((const float2*)(D2 + (size_t)b * NN + rank * 512))[t];
        thr2.x = ALPHA * fabsf(d1.x); thr2.y = ALPHA * fabsf(d1.y);
        dv2.x = 1.0f / (1.0f + 2.0f * ALPHA * d2.x * d2.x);
        dv2.y = 1.0f / (1.0f + 2.0f * ALPHA * d2.y * d2.y);
    }
    __syncthreads();
    cluster_sync_();

    // pass1 per-warp constants: warp w -> m-tile rows 16*(w&7), k-half w>>3
    const int p1_m0 = (w & 7) * 16, p1_kh = w >> 3;
    const uint32_t p1_addr = aA + (uint32_t)(p1_m0 + (l & 15)) * 1040u
                           + (uint32_t)(p1_kh * 512) + (uint32_t)((l >> 4) << 4);
    const int bc = l & 3;              // tid%4: b-frag k-subgroup
    // pass2: warp w -> m-tiles (cols) 2w, 2w+1
    const uint32_t p2_rowoff = (uint32_t)((l & 7) + ((l >> 4) << 3)) * 1040u
                             + (uint32_t)((l & 8) << 1);

    for (int it = 0; it < ITERS; it++) {
        const int buf = it & 1;
        // --- elementwise: soft-threshold, y = 2x_half - z, split to fp16 hi/lo
        if (t < 256) {
            float a0 = z2.x - thr2.x, c0 = z2.x + thr2.x;
            float a1 = z2.y - thr2.y, c1 = z2.y + thr2.y;
            xh2.x = (a0 > 0.f) ? a0 * dv2.x : ((c0 < 0.f) ? c0 * dv2.x : 0.f);
            xh2.y = (a1 > 0.f) ? a1 * dv2.y : ((c1 < 0.f) ? c1 * dv2.y : 0.f);
            yv2.x = 2.0f * xh2.x - z2.x;
            yv2.y = 2.0f * xh2.y - z2.y;
            __half2 hy = __floats2half2_rn(yv2.x, yv2.y);
            float2 fy = __half22float2(hy);
            __half2 ly = __floats2half2_rn(yv2.x - fy.x, yv2.y - fy.y);
            ((uint32_t*)(sm + OFF_YH))[t] = *(uint32_t*)&hy;
            ((uint32_t*)(sm + OFF_YL))[t] = *(uint32_t*)&ly;
        }
        __syncthreads();                                   // bar1: y ready

        // --- pass 1 (HMMA, split acc): r_partial[kh] ---
        {
            float ch0 = 0.f, ch1 = 0.f, ch2 = 0.f, ch3 = 0.f;
            float cl0 = 0.f, cl1 = 0.f, cl2 = 0.f, cl3 = 0.f;
            const uint32_t* yh = (const uint32_t*)(sm + OFF_YH) + p1_kh * 128;
            const uint32_t* yl = (const uint32_t*)(sm + OFF_YL) + p1_kh * 128;
            uint32_t addr = p1_addr;
#pragma unroll
            for (int kt = 0; kt < 16; kt++) {
                uint32_t a0, a1, a2, a3;
                ldsm_x4(a0, a1, a2, a3, addr);
                addr += 32u;                                // +16 halves
                int kb = kt * 8 + bc;
                mma16816(ch0, ch1, ch2, ch3, a0, a1, a2, a3, yh[kb], yh[kb + 4]);
                mma16816(cl0, cl1, cl2, cl3, a0, a1, a2, a3, yl[kb], yl[kb + 4]);
            }
            if ((l & 3) == 0) {
                float* srp = sm + (p1_kh ? OFF_SR1 : OFF_SR0);
                srp[p1_m0 + (l >> 2)]     = ch0 + cl0;
                srp[p1_m0 + 8 + (l >> 2)] = ch2 + cl2;
            }
        }
        __syncthreads();                                   // bar2: partials ready

        // --- exchange + r_total (t<128) ---
        if (t < 128) {
            float s = sm[OFF_SR0 + t] + sm[OFF_SR1 + t];
            st_cluster_f32(peer + (uint32_t)(OFF_REM + buf * 128 + t) * 4u, s);
            mbar_arrive_remote(peer + OFF_MB * 4u + 8u * buf);
            mbar_wait_acq(sbase + OFF_MB * 4u + 8u * buf, (uint32_t)((it >> 1) & 1));
            sm[OFF_RT + t] = s + sm[OFF_REM + buf * 128 + t] - sm[OFF_B + t];
        }
        __syncthreads();                                   // bar3: rt ready

        // --- u = C * rt (ALL 512 threads, 4/row, CONFLICT-FREE stagger) ---
        {
            int i = t >> 2, q = t & 3, h0 = i & 7;
            float accu = 0.0f;
#pragma unroll
            for (int m = 0; m < 8; m++) {
                int j = 4 * (q + 4 * ((h0 + m) & 7));       // word offsets 4q+16(s&1): distinct banks
                float4 c4 = *(const float4*)(sm + OFF_C + i * 128 + j);
                float4 r4 = *(const float4*)(sm + OFF_RT + j);
                accu += c4.x * r4.x + c4.y * r4.y + c4.z * r4.z + c4.w * r4.w;
            }
            accu += __shfl_xor_sync(0xffffffffu, accu, 1);
            accu += __shfl_xor_sync(0xffffffffu, accu, 2);  // 4 lanes hold u_i
            float un = __shfl_down_sync(0xffffffffu, accu, 4);  // u_{i+1}
            if ((t & 7) == 0) {
                __half2 hu = __floats2half2_rn(accu, un);
                float2 fu = __half22float2(hu);
                __half2 lu = __floats2half2_rn(accu - fu.x, un - fu.y);
                ((uint32_t*)(sm + OFF_UH))[t >> 3] = *(uint32_t*)&hu;
                ((uint32_t*)(sm + OFF_UL))[t >> 3] = *(uint32_t*)&lu;
            }
        }
        __syncthreads();                                   // bar4: u ready

        // --- pass 2 (HMMA trans, split acc): corr = A^T * u ---
        {
            const uint32_t* uh = (const uint32_t*)(sm + OFF_UH);
            const uint32_t* ul = (const uint32_t*)(sm + OFF_UL);
#pragma unroll
            for (int mi = 0; mi < 2; mi++) {
                int mt = 2 * w + mi, cc0 = mt * 16;
                float dh0 = 0.f, dh1 = 0.f, dh2 = 0.f, dh3 = 0.f;
                float dl0 = 0.f, dl1 = 0.f, dl2 = 0.f, dl3 = 0.f;
                uint32_t addr = aA + p2_rowoff + (uint32_t)(cc0 * 2);
#pragma unroll
                for (int kt = 0; kt < 8; kt++) {
                    uint32_t a0, a1, a2, a3;
                    ldsm_x4t(a0, a1, a2, a3, addr);
                    addr += 16u * 1040u;                    // +16 rows
                    int kb = kt * 8 + bc;
                    mma16816(dh0, dh1, dh2, dh3, a0, a1, a2, a3, uh[kb], uh[kb + 4]);
                    mma16816(dl0, dl1, dl2, dl3, a0, a1, a2, a3, ul[kb], ul[kb + 4]);
                }
                if ((l & 3) == 0) {
                    sm[OFF_CORR + cc0 + (l >> 2)]     = dh0 + dl0;
                    sm[OFF_CORR + cc0 + 8 + (l >> 2)] = dh2 + dl2;
                }
            }
        }
        __syncthreads();                                   // bar5: corr ready

        // --- epilogue: z' = x_half - corr, x_new = y - corr ---
        if (t < 256) {
            float2 cr = *(const float2*)(sm + OFF_CORR + 2 * t);
            z2.x = xh2.x - cr.x; z2.y = xh2.y - cr.y;
            yv2.x -= cr.x; yv2.y -= cr.y;                  // x_new
        }
    }

    if (t < 256)
        ((float2*)(out + (size_t)b * NN + rank * 512))[t] = yv2;
    cluster_sync_();
}

// --------------------------------------------------------------------------
extern "C" void kernel_launch(void* const* d_in, const int* in_sizes, int n_in,
                              void* d_out, int out_size) {
    const float* A  = (const float*)d_in[0];
    const float* bv = (const float*)d_in[1];
    const float* D1 = (const float*)d_in[2];
    const float* D2 = (const float*)d_in[3];
    float* out = (float*)d_out;

    cudaFuncSetAttribute(k_inv,  cudaFuncAttributeMaxDynamicSharedMemorySize, 66052);
    cudaFuncSetAttribute(k_iter, cudaFuncAttributeMaxDynamicSharedMemorySize, SMEM_WORDS * 4);

    k_aat<<<BSZ, 256>>>(A);        // fused convert + AAT
    k_inv<<<BSZ, 512, 66052>>>();
    k_iter<<<BSZ * 2, 512, SMEM_WORDS * 4>>>(bv, D1, D2, out);
}

// round 16
// speedup vs baseline: 1.3246x; 1.1342x over previous
#include <cuda_runtime.h>
#include <cuda_fp16.h>
#include <cstdint>

#define BSZ   256
#define MM    128
#define NN    1024
#define ITERS 100
#define ALPHA 0.1f

__device__ __half g_Ah[(size_t)BSZ * MM * NN];
__device__ float  g_C [(size_t)BSZ * MM * MM];   // AAT -> inverse (in place)

__device__ __forceinline__ uint32_t smem_u32(const void* p) {
    uint32_t a;
    asm("{ .reg .u64 t; cvta.to.shared.u64 t, %1; cvt.u32.u64 %0, t; }" : "=r"(a) : "l"(p));
    return a;
}
__device__ __forceinline__ uint32_t mapa_rank(uint32_t addr, uint32_t trank) {
    uint32_t r;
    asm("mapa.shared::cluster.u32 %0, %1, %2;" : "=r"(r) : "r"(addr), "r"(trank));
    return r;
}
__device__ __forceinline__ void cluster_sync_() {
    asm volatile("barrier.cluster.arrive.aligned;" ::: "memory");
    asm volatile("barrier.cluster.wait.aligned;"   ::: "memory");
}
__device__ __forceinline__ void st_cluster_f32(uint32_t addr, float v) {
    asm volatile("st.shared::cluster.f32 [%0], %1;" :: "r"(addr), "f"(v) : "memory");
}
__device__ __forceinline__ void mbar_init(uint32_t a, uint32_t c) {
    asm volatile("mbarrier.init.shared.b64 [%0], %1;" :: "r"(a), "r"(c) : "memory");
}
__device__ __forceinline__ void mbar_arrive_remote(uint32_t ra) {
    asm volatile("mbarrier.arrive.release.cluster.shared::cluster.b64 _, [%0];" :: "r"(ra) : "memory");
}
__device__ __forceinline__ void mbar_wait_acq(uint32_t mb, uint32_t par) {
    asm volatile(
        "{\n\t.reg .pred P;\n\t"
        "WL%=:\n\t"
        "mbarrier.try_wait.parity.acquire.cluster.shared::cta.b64 P, [%0], %1, 0x989680;\n\t"
        "@P bra.uni WD%=;\n\t"
        "bra.uni WL%=;\n\t"
        "WD%=:\n\t}" :: "r"(mb), "r"(par) : "memory");
}
__device__ __forceinline__ void ldsm_x4(uint32_t& a0, uint32_t& a1, uint32_t& a2, uint32_t& a3, uint32_t addr) {
    asm volatile("ldmatrix.sync.aligned.m8n8.x4.shared.b16 {%0,%1,%2,%3}, [%4];"
                 : "=r"(a0), "=r"(a1), "=r"(a2), "=r"(a3) : "r"(addr));
}
__device__ __forceinline__ void ldsm_x4t(uint32_t& a0, uint32_t& a1, uint32_t& a2, uint32_t& a3, uint32_t addr) {
    asm volatile("ldmatrix.sync.aligned.m8n8.x4.trans.shared.b16 {%0,%1,%2,%3}, [%4];"
                 : "=r"(a0), "=r"(a1), "=r"(a2), "=r"(a3) : "r"(addr));
}
__device__ __forceinline__ void mma16816(float& c0, float& c1, float& c2, float& c3,
                                         uint32_t a0, uint32_t a1, uint32_t a2, uint32_t a3,
                                         uint32_t b0, uint32_t b1) {
    asm volatile("mma.sync.aligned.m16n8k16.row.col.f32.f16.f16.f32 "
                 "{%0,%1,%2,%3},{%4,%5,%6,%7},{%8,%9},{%0,%1,%2,%3};"
                 : "+f"(c0), "+f"(c1), "+f"(c2), "+f"(c3)
                 : "r"(a0), "r"(a1), "r"(a2), "r"(a3), "r"(b0), "r"(b1));
}

// --------------------------------------------------------------------------
// k_aat (HMMA, fused fp32->fp16 convert) — verified R15
// --------------------------------------------------------------------------
#define AT_PITCH_B 272
__global__ void __launch_bounds__(256) k_aat(const float* __restrict__ A32) {
    __shared__ __half tile[128 * (AT_PITCH_B / 2)];
    const int b = blockIdx.x, t = threadIdx.x, w = t >> 5, l = t & 31;
    const uint32_t tbase = smem_u32(tile);
    uint2* gah = (uint2*)(g_Ah + (size_t)b * MM * NN);

    float acc[16][4];
#pragma unroll
    for (int nt = 0; nt < 16; nt++)
#pragma unroll
        for (int q = 0; q < 4; q++) acc[nt][q] = 0.0f;

    const int m0 = w * 16;
    const uint32_t aAddr = tbase + (uint32_t)(m0 + (l & 15)) * AT_PITCH_B
                         + (uint32_t)((l >> 4) << 4);
    const int bg = l >> 3;
    const uint32_t bAddr0 = tbase + (uint32_t)((l & 7) + ((bg >> 1) << 3)) * AT_PITCH_B
                          + (uint32_t)((bg & 1) << 4);

    for (int kc = 0; kc < 8; kc++) {
#pragma unroll
        for (int q = 0; q < 16; q++) {
            int i = t + 256 * q, r = i >> 5, c4 = i & 31;
            float4 v = *(const float4*)(A32 + ((size_t)(b * MM + r)) * NN + kc * 128 + c4 * 4);
            uint2 hv;
            __half2 h0 = __floats2half2_rn(v.x, v.y);
            __half2 h1 = __floats2half2_rn(v.z, v.w);
            hv.x = *(uint32_t*)&h0; hv.y = *(uint32_t*)&h1;
            *(uint2*)((char*)tile + r * AT_PITCH_B + c4 * 8) = hv;
            gah[(size_t)r * 256 + kc * 32 + c4] = hv;
        }
        __syncthreads();

#pragma unroll
        for (int kt = 0; kt < 8; kt++) {
            uint32_t a0, a1, a2, a3;
            ldsm_x4(a0, a1, a2, a3, aAddr + (uint32_t)(kt * 32));
#pragma unroll
            for (int nt = 0; nt < 16; nt += 2) {
                uint32_t r0, r1, r2, r3;
                ldsm_x4(r0, r1, r2, r3,
                        bAddr0 + (uint32_t)(nt * 8) * AT_PITCH_B + (uint32_t)(kt * 32));
                mma16816(acc[nt][0],   acc[nt][1],   acc[nt][2],   acc[nt][3],
                         a0, a1, a2, a3, r0, r1);
                mma16816(acc[nt+1][0], acc[nt+1][1], acc[nt+1][2], acc[nt+1][3],
                         a0, a1, a2, a3, r2, r3);
            }
        }
        __syncthreads();
    }

    float* Cb = g_C + (size_t)b * MM * MM;
    const int r0 = m0 + (l >> 2), c0 = 2 * (l & 3);
#pragma unroll
    for (int nt = 0; nt < 16; nt++) {
        *(float2*)&Cb[(size_t)r0 * MM + nt * 8 + c0]       = make_float2(acc[nt][0], acc[nt][1]);
        *(float2*)&Cb[(size_t)(r0 + 8) * MM + nt * 8 + c0] = make_float2(acc[nt][2], acc[nt][3]);
    }
}

// --------------------------------------------------------------------------
// k_inv: BLOCKED Gauss-Jordan (rank-8 updates), in place on g_C.
// Per block [k0, k0+8): snapshot panel G = A[:,blk]; invert 8x8 diag block B
// (warp 0, warp-sync); pivot rows R = Binv*R_old (block cols := Binv);
// non-pivot rows A -= G*R (block-col groups drop A term -> -G*Binv).
// 4 __syncthreads per block (64 total vs 384 scalar).
// --------------------------------------------------------------------------
__global__ void __launch_bounds__(512) k_inv() {
    extern __shared__ float sm[];
    float* sM = sm;              // 16384
    float* sG = sm + 16384;      // 128*8 = 1024
    float* sR = sm + 17408;      // 8*128 = 1024
    float* sB = sm + 18432;      // 64 (B -> Binv)
    const int b = blockIdx.x, t = threadIdx.x;
    float* Cb = g_C + (size_t)b * MM * MM;

    for (int i = t; i < 4096; i += 512) ((float4*)sM)[i] = ((const float4*)Cb)[i];
    __syncthreads();

    for (int blk = 0; blk < 16; blk++) {
        const int k0 = blk * 8;

        // (a) snapshot panel G = sM[:, k0:k0+8]  (256 threads, float4 each)
        if (t < 256) {
            int i = t >> 1, q = t & 1;
            *(float4*)&sG[i * 8 + 4 * q] = *(const float4*)&sM[i * 128 + k0 + 4 * q];
        }
        __syncthreads();                                   // bar a: G ready

        // (b) warp 0: invert B (8x8) in sB, warp-synchronous
        if (t < 32) {
            sB[t]      = sG[(k0 + (t >> 3)) * 8 + (t & 7)];
            sB[t + 32] = sG[(k0 + 4 + (t >> 3)) * 8 + (t & 7)];
            __syncwarp();
#pragma unroll
            for (int k = 0; k < 8; k++) {
                float ipiv = 1.0f / sB[k * 8 + k];
                int r0 = t >> 3, c0 = t & 7, r1 = r0 + 4;
                float v0 = sB[t], v1 = sB[t + 32];
                float f0 = sB[r0 * 8 + k], f1 = sB[r1 * 8 + k];
                float mk = sB[k * 8 + c0];
                __syncwarp();
                float n0, n1;
                if (r0 == k) n0 = (c0 == k) ? ipiv : v0 * ipiv;
                else         n0 = (c0 == k) ? -f0 * ipiv : v0 - f0 * (mk * ipiv);
                if (r1 == k) n1 = (c0 == k) ? ipiv : v1 * ipiv;
                else         n1 = (c0 == k) ? -f1 * ipiv : v1 - f1 * (mk * ipiv);
                sB[t] = n0; sB[t + 32] = n1;
                __syncwarp();
            }
        }
        __syncthreads();                                   // bar b: Binv ready

        // (c) pivot rows: sR = Binv * R_old; block cols overridden with Binv
        {
            int idx = 2 * t;                   // 1024 elems, float2 per thread
            int r = idx >> 7, j = idx & 127;
            float a0 = 0.f, a1 = 0.f;
#pragma unroll
            for (int c = 0; c < 8; c++) {
                float bv = sB[r * 8 + c];
                float2 mrow = *(const float2*)&sM[(k0 + c) * 128 + j];
                a0 += bv * mrow.x;
                a1 += bv * mrow.y;
            }
            if (j     >= k0 && j     < k0 + 8) a0 = sB[r * 8 + (j - k0)];
            if (j + 1 >= k0 && j + 1 < k0 + 8) a1 = sB[r * 8 + (j + 1 - k0)];
            *(float2*)&sR[r * 128 + j] = make_float2(a0, a1);
        }
        __syncthreads();                                   // bar c: sR ready

        // (d1) write pivot rows final  (disjoint from (d2)'s rows)
        {
            int idx = 2 * t;
            int r = idx >> 7, j = idx & 127;
            *(float2*)&sM[(k0 + r) * 128 + j] = *(const float2*)&sR[r * 128 + j];
        }
        // (d2) rank-8 update of non-pivot rows
        {
            int j4 = t & 31;                   // float4 col group
            int i0 = (t >> 5) * 8;             // 8 rows per thread
            float4 r4[8];
#pragma unroll
            for (int c = 0; c < 8; c++) r4[c] = *(const float4*)&sR[c * 128 + 4 * j4];
            const bool inb = (4 * j4 >= k0) && (4 * j4 < k0 + 8);
#pragma unroll
            for (int ii = 0; ii < 8; ii++) {
                int i = i0 + ii;
                if (i >= k0 && i < k0 + 8) continue;       // pivot rows done in (d1)
                float4 g0 = *(const float4*)&sG[i * 8];
                float4 g1 = *(const float4*)&sG[i * 8 + 4];
                float4 a = inb ? make_float4(0.f, 0.f, 0.f, 0.f)
                               : *(const float4*)&sM[i * 128 + 4 * j4];
                a.x -= g0.x*r4[0].x + g0.y*r4[1].x + g0.z*r4[2].x + g0.w*r4[3].x
                     + g1.x*r4[4].x + g1.y*r4[5].x + g1.z*r4[6].x + g1.w*r4[7].x;
                a.y -= g0.x*r4[0].y + g0.y*r4[1].y + g0.z*r4[2].y + g0.w*r4[3].y
                     + g1.x*r4[4].y + g1.y*r4[5].y + g1.z*r4[6].y + g1.w*r4[7].y;
                a.z -= g0.x*r4[0].z + g0.y*r4[1].z + g0.z*r4[2].z + g0.w*r4[3].z
                     + g1.x*r4[4].z + g1.y*r4[5].z + g1.z*r4[6].z + g1.w*r4[7].z;
                a.w -= g0.x*r4[0].w + g0.y*r4[1].w + g0.z*r4[2].w + g0.w*r4[3].w
                     + g1.x*r4[4].w + g1.y*r4[5].w + g1.z*r4[6].w + g1.w*r4[7].w;
                *(float4*)&sM[i * 128 + 4 * j4] = a;
            }
        }
        __syncthreads();                                   // bar d: block done
    }

    for (int i = t; i < 4096; i += 512) ((float4*)Cb)[i] = ((const float4*)sM)[i];
}

// Iterations: EXACT R15 kernel (champion core) --------------------------------
#define APAD_U4  65
#define OFF_C    0                     // 16384 f
#define OFF_A    16384                 // 33280 w (128*260 u32)
#define OFF_YH   49664                 // 256 u32 (half2 y_hi)
#define OFF_YL   49920                 // 256 u32
#define OFF_B    50176                 // 128 f
#define OFF_SR0  50304                 // 128 f (khalf 0 partial)
#define OFF_SR1  50432                 // 128 f (khalf 1 partial)
#define OFF_REM  50560                 // 256 f (peer partial, 2 bufs)
#define OFF_RT   50816                 // 128 f
#define OFF_UH   50944                 // 64 u32 (half2 u_hi)
#define OFF_UL   51008                 // 64 u32
#define OFF_CORR 51072                 // 512 f
#define OFF_MB   51584                 // 2 x u64 mbarriers
#define SMEM_WORDS 51588               // 206352 bytes

__global__ void __launch_bounds__(512, 1) __cluster_dims__(2, 1, 1)
k_iter(const float* __restrict__ bvec, const float* __restrict__ D1,
       const float* __restrict__ D2, float* __restrict__ out) {
    extern __shared__ float sm[];
    const int t = threadIdx.x, w = t >> 5, l = t & 31;
    const int b = blockIdx.x >> 1;
    const uint32_t rank = blockIdx.x & 1;
    const uint32_t sbase = smem_u32(sm);
    const uint32_t peer = mapa_rank(sbase, rank ^ 1u);
    const uint32_t aA = sbase + OFF_A * 4u;

    {   // load C, padded A-half, b
        float4* d = (float4*)(sm + OFF_C);
        const float4* s = (const float4*)(g_C + (size_t)b * MM * MM);
#pragma unroll
        for (int q = 0; q < 8; q++) d[t + 512 * q] = s[t + 512 * q];
        uint4* da = (uint4*)(sm + OFF_A);
        const uint4* sa = (const uint4*)(g_Ah + (size_t)b * MM * NN + (size_t)rank * 512);
#pragma unroll
        for (int q = 0; q < 16; q++) {
            int i = t + 512 * q, r = i >> 6, c4 = i & 63;
            da[r * APAD_U4 + c4] = sa[(size_t)r * 128 + c4];
        }
        if (t < 128) sm[OFF_B + t] = bvec[(size_t)b * MM + t];
        if (t == 0) {
            mbar_init(sbase + OFF_MB * 4u, 128);
            mbar_init(sbase + OFF_MB * 4u + 8u, 128);
        }
    }

    float2 thr2 = make_float2(0.f, 0.f), dv2 = make_float2(0.f, 0.f);
    float2 z2 = make_float2(0.f, 0.f), xh2, yv2 = make_float2(0.f, 0.f);
    if (t < 256) {
        float2 d1 = ((const float2*)(D1 + (size_t)b * NN + rank * 512))[t];
        float2 d2 = ((const float2*)(D2 + (size_t)b * NN + rank * 512))[t];
        thr2.x = ALPHA * fabsf(d1.x); thr2.y = ALPHA * fabsf(d1.y);
        dv2.x = 1.0f / (1.0f + 2.0f * ALPHA * d2.x * d2.x);
        dv2.y = 1.0f / (1.0f + 2.0f * ALPHA * d2.y * d2.y);
    }
    __syncthreads();
    cluster_sync_();

    const int p1_m0 = (w & 7) * 16, p1_kh = w >> 3;
    const uint32_t p1_addr = aA + (uint32_t)(p1_m0 + (l & 15)) * 1040u
                           + (uint32_t)(p1_kh * 512) + (uint32_t)((l >> 4) << 4);
    const int bc = l & 3;
    const uint32_t p2_rowoff = (uint32_t)((l & 7) + ((l >> 4) << 3)) * 1040u
                             + (uint32_t)((l & 8) << 1);

    for (int it = 0; it < ITERS; it++) {
        const int buf = it & 1;
        if (t < 256) {
            float a0 = z2.x - thr2.x, c0 = z2.x + thr2.x;
            float a1 = z2.y - thr2.y, c1 = z2.y + thr2.y;
            xh2.x = (a0 > 0.f) ? a0 * dv2.x : ((c0 < 0.f) ? c0 * dv2.x : 0.f);
            xh2.y = (a1 > 0.f) ? a1 * dv2.y : ((c1 < 0.f) ? c1 * dv2.y : 0.f);
            yv2.x = 2.0f * xh2.x - z2.x;
            yv2.y = 2.0f * xh2.y - z2.y;
            __half2 hy = __floats2half2_rn(yv2.x, yv2.y);
            float2 fy = __half22float2(hy);
            __half2 ly = __floats2half2_rn(yv2.x - fy.x, yv2.y - fy.y);
            ((uint32_t*)(sm + OFF_YH))[t] = *(uint32_t*)&hy;
            ((uint32_t*)(sm + OFF_YL))[t] = *(uint32_t*)&ly;
        }
        __syncthreads();                                   // bar1: y ready

        {
            float ch0 = 0.f, ch1 = 0.f, ch2 = 0.f, ch3 = 0.f;
            float cl0 = 0.f, cl1 = 0.f, cl2 = 0.f, cl3 = 0.f;
            const uint32_t* yh = (const uint32_t*)(sm + OFF_YH) + p1_kh * 128;
            const uint32_t* yl = (const uint32_t*)(sm + OFF_YL) + p1_kh * 128;
            uint32_t addr = p1_addr;
#pragma unroll
            for (int kt = 0; kt < 16; kt++) {
                uint32_t a0, a1, a2, a3;
                ldsm_x4(a0, a1, a2, a3, addr);
                addr += 32u;
                int kb = kt * 8 + bc;
                mma16816(ch0, ch1, ch2, ch3, a0, a1, a2, a3, yh[kb], yh[kb + 4]);
                mma16816(cl0, cl1, cl2, cl3, a0, a1, a2, a3, yl[kb], yl[kb + 4]);
            }
            if ((l & 3) == 0) {
                float* srp = sm + (p1_kh ? OFF_SR1 : OFF_SR0);
                srp[p1_m0 + (l >> 2)]     = ch0 + cl0;
                srp[p1_m0 + 8 + (l >> 2)] = ch2 + cl2;
            }
        }
        __syncthreads();                                   // bar2: partials ready

        if (t < 128) {
            float s = sm[OFF_SR0 + t] + sm[OFF_SR1 + t];
            st_cluster_f32(peer + (uint32_t)(OFF_REM + buf * 128 + t) * 4u, s);
            mbar_arrive_remote(peer + OFF_MB * 4u + 8u * buf);
            mbar_wait_acq(sbase + OFF_MB * 4u + 8u * buf, (uint32_t)((it >> 1) & 1));
            sm[OFF_RT + t] = s + sm[OFF_REM + buf * 128 + t] - sm[OFF_B + t];
        }
        __syncthreads();                                   // bar3: rt ready

        {
            int i = t >> 2, q = t & 3, h0 = i & 7;
            float accu = 0.0f;
#pragma unroll
            for (int m = 0; m < 8; m++) {
                int j = 4 * (q + 4 * ((h0 + m) & 7));
                float4 c4 = *(const float4*)(sm + OFF_C + i * 128 + j);
                float4 r4 = *(const float4*)(sm + OFF_RT + j);
                accu += c4.x * r4.x + c4.y * r4.y + c4.z * r4.z + c4.w * r4.w;
            }
            accu += __shfl_xor_sync(0xffffffffu, accu, 1);
            accu += __shfl_xor_sync(0xffffffffu, accu, 2);
            float un = __shfl_down_sync(0xffffffffu, accu, 4);
            if ((t & 7) == 0) {
                __half2 hu = __floats2half2_rn(accu, un);
                float2 fu = __half22float2(hu);
                __half2 lu = __floats2half2_rn(accu - fu.x, un - fu.y);
                ((uint32_t*)(sm + OFF_UH))[t >> 3] = *(uint32_t*)&hu;
                ((uint32_t*)(sm + OFF_UL))[t >> 3] = *(uint32_t*)&lu;
            }
        }
        __syncthreads();                                   // bar4: u ready

        {
            const uint32_t* uh = (const uint32_t*)(sm + OFF_UH);
            const uint32_t* ul = (const uint32_t*)(sm + OFF_UL);
#pragma unroll
            for (int mi = 0; mi < 2; mi++) {
                int mt = 2 * w + mi, cc0 = mt * 16;
                float dh0 = 0.f, dh1 = 0.f, dh2 = 0.f, dh3 = 0.f;
                float dl0 = 0.f, dl1 = 0.f, dl2 = 0.f, dl3 = 0.f;
                uint32_t addr = aA + p2_rowoff + (uint32_t)(cc0 * 2);
#pragma unroll
                for (int kt = 0; kt < 8; kt++) {
                    uint32_t a0, a1, a2, a3;
                    ldsm_x4t(a0, a1, a2, a3, addr);
                    addr += 16u * 1040u;
                    int kb = kt * 8 + bc;
                    mma16816(dh0, dh1, dh2, dh3, a0, a1, a2, a3, uh[kb], uh[kb + 4]);
                    mma16816(dl0, dl1, dl2, dl3, a0, a1, a2, a3, ul[kb], ul[kb + 4]);
                }
                if ((l & 3) == 0) {
                    sm[OFF_CORR + cc0 + (l >> 2)]     = dh0 + dl0;
                    sm[OFF_CORR + cc0 + 8 + (l >> 2)] = dh2 + dl2;
                }
            }
        }
        __syncthreads();                                   // bar5: corr ready

        if (t < 256) {
            float2 cr = *(const float2*)(sm + OFF_CORR + 2 * t);
            z2.x = xh2.x - cr.x; z2.y = xh2.y - cr.y;
            yv2.x -= cr.x; yv2.y -= cr.y;
        }
    }

    if (t < 256)
        ((float2*)(out + (size_t)b * NN + rank * 512))[t] = yv2;
    cluster_sync_();
}

// --------------------------------------------------------------------------
extern "C" void kernel_launch(void* const* d_in, const int* in_sizes, int n_in,
                              void* d_out, int out_size) {
    const float* A  = (const float*)d_in[0];
    const float* bv = (const float*)d_in[1];
    const float* D1 = (const float*)d_in[2];
    const float* D2 = (const float*)d_in[3];
    float* out = (float*)d_out;

    cudaFuncSetAttribute(k_inv,  cudaFuncAttributeMaxDynamicSharedMemorySize, 73984);
    cudaFuncSetAttribute(k_iter, cudaFuncAttributeMaxDynamicSharedMemorySize, SMEM_WORDS * 4);

    k_aat<<<BSZ, 256>>>(A);        // fused convert + AAT
    k_inv<<<BSZ, 512, 73984>>>();
    k_iter<<<BSZ * 2, 512, SMEM_WORDS * 4>>>(bv, D1, D2, out);
}